// round 13
// baseline (speedup 1.0000x reference)
#include <cuda_runtime.h>
#include <cuda_fp16.h>
#include <math.h>
#include <stdint.h>

#define BATCH 64
#define NCC   1024
#define NTT   1024
#define HID   512
#define NPTS  (BATCH*(NCC+NTT))   /* 131072 */
#define NCTX  (BATCH*NCC)         /* 65536  */
#define NP    576                 /* padded 513 -> 576 = 18*32 */
#define NB    32

/* ------------------- global scratch (static, no allocs) --------------- */
__device__ __half g_hA[(size_t)NPTS*HID];
__device__ __half g_hB[(size_t)NPTS*HID];
__device__ float  g_bufF[(size_t)NPTS*HID];    /* fp32 target features */
__device__ __half g_PT[(size_t)BATCH*NP*NCC];  /* PhiT [b][r][n]       */
__device__ __half g_W1h[HID*HID];
__device__ __half g_W2h[HID*HID];
__device__ __half g_Wrh[HID*HID];
__device__ float g_cov [(size_t)BATCH*NP*NP];
__device__ float g_xty [BATCH*NP];
__device__ float g_w   [BATCH*NP];
__device__ float g_stats[BATCH*2];

/* ----------------------- PTX helpers (sm_80-era only) ----------------- */
__device__ __forceinline__ uint32_t smem_u32(const void* p) {
    uint32_t a;
    asm("{ .reg .u64 t; cvta.to.shared.u64 t, %1; cvt.u32.u64 %0, t; }" : "=r"(a) : "l"(p));
    return a;
}

__device__ __forceinline__ void cp16(uint32_t dst, const void* src) {
    asm volatile("cp.async.cg.shared.global [%0], [%1], 16;" :: "r"(dst), "l"(src));
}
#define CP_COMMIT() asm volatile("cp.async.commit_group;" ::: "memory")
#define CP_WAIT(n)  asm volatile("cp.async.wait_group %0;" :: "n"(n) : "memory")

__device__ __forceinline__ void ldsm_x4(uint32_t* r, uint32_t addr) {
    asm volatile("ldmatrix.sync.aligned.m8n8.x4.shared.b16 {%0,%1,%2,%3}, [%4];"
        : "=r"(r[0]), "=r"(r[1]), "=r"(r[2]), "=r"(r[3]) : "r"(addr));
}
__device__ __forceinline__ void ldsm_x2(uint32_t* r, uint32_t addr) {
    asm volatile("ldmatrix.sync.aligned.m8n8.x2.shared.b16 {%0,%1}, [%2];"
        : "=r"(r[0]), "=r"(r[1]) : "r"(addr));
}

__device__ __forceinline__ void mma16816(float* c,
        uint32_t a0, uint32_t a1, uint32_t a2, uint32_t a3,
        uint32_t b0, uint32_t b1) {
    asm volatile(
        "mma.sync.aligned.m16n8k16.row.col.f32.f16.f16.f32 "
        "{%0,%1,%2,%3}, {%4,%5,%6,%7}, {%8,%9}, {%0,%1,%2,%3};"
        : "+f"(c[0]), "+f"(c[1]), "+f"(c[2]), "+f"(c[3])
        : "r"(a0), "r"(a1), "r"(a2), "r"(a3), "r"(b0), "r"(b1));
}

/* polynomial sine, valid |x| <= ~2 (Taylor deg-9, err < 5e-5 at 2.0,
   < 4e-6 on [-pi/2,pi/2]) — pure FMA, no MUFU */
__device__ __forceinline__ float sin_poly(float x) {
    float x2 = x * x;
    float p = fmaf(x2, 2.75573192e-6f, -1.98412698e-4f);
    p = fmaf(x2, p, 8.33333333e-3f);
    p = fmaf(x2, p, -1.66666667e-1f);
    return fmaf(x * x2, p, x);
}

/* accurate fp32 sin for |arg| up to ~1000: Cody-Waite mod pi + poly */
__device__ __forceinline__ float sin_cw(float arg) {
    float k = rintf(arg * 0.3183098861837907f);
    float r = fmaf(-k, 3.14159274101257324e+0f, arg);
    r = fmaf(-k, -8.74227765734758577e-8f, r);
    float s = sin_poly(r);
    int ki = (int)k;
    return (ki & 1) ? -s : s;
}

/* ---------------- layer 0: h0 = sin(30*(x*W0 + b0)) ------------------- */
__global__ void layer0_kernel(const float* __restrict__ xc,
                              const float* __restrict__ xt,
                              const float* __restrict__ W0,
                              const float* __restrict__ b0) {
    size_t idx = (size_t)blockIdx.x * blockDim.x + threadIdx.x;
    int p = (int)(idx >> 9);
    int j = (int)(idx & 511);
    float x = (p < NCTX) ? xc[p] : xt[p - NCTX];
    float arg = 30.0f * fmaf(x, W0[j], b0[j]);
    g_hA[idx] = __float2half_rn(sin_cw(arg));
}

/* ------------- weight prep: transpose all 3 weights to fp16 ----------- */
__global__ void prep_w_kernel(const float* __restrict__ W1,
                              const float* __restrict__ W2,
                              const float* __restrict__ Wr) {
    int i = blockIdx.x * 256 + threadIdx.x;
    int k = i >> 9, n = i & 511;
    g_W1h[n * 512 + k] = __float2half_rn(W1[i]);
    g_W2h[n * 512 + k] = __float2half_rn(W2[i]);
    g_Wrh[n * 512 + k] = __float2half_rn(Wr[i]);
}

/* ---- init PhiT rows 512..575: row 512 = ones, rest zero -------------- */
__global__ void pt_init_kernel() {
    int i = blockIdx.x * 256 + threadIdx.x;
    int n   = i & 1023;
    int row = (i >> 10) & 63;
    int b   = i >> 16;
    size_t o = ((size_t)b * NP + 512 + row) * 1024 + n;
    g_PT[o] = __float2half_rn(row == 0 ? 1.0f : 0.0f);
}

/* -------- HMMA fp16 GEMM: C = act(A @ W + bias) ----------------------- */
#define LDS 40
#define ARR_ELEMS (128*LDS)
#define STAGE_ELEMS (2*ARR_ELEMS)
#define NSTG 3
#define GEMM_SMEM (NSTG*STAGE_ELEMS*2)

template<bool SIN, bool LAST>
__global__ void __launch_bounds__(256, 2) mma_gemm(
    const __half* __restrict__ A,
    const __half* __restrict__ Wh,
    const float* __restrict__ bias,
    __half* __restrict__ O,
    float* __restrict__ Of)
{
    extern __shared__ __half sm[];
    int tid = threadIdx.x;
    int lane = tid & 31, wid = tid >> 5;
    int wm = wid >> 2, wn = wid & 3;
    int m0 = blockIdx.y * 128;
    int n0 = blockIdx.x * 128;

    uint32_t sbase = smem_u32(sm);

    float acc[4][4][4];
#pragma unroll
    for (int a = 0; a < 4; a++)
#pragma unroll
        for (int b = 0; b < 4; b++)
#pragma unroll
            for (int c = 0; c < 4; c++) acc[a][b][c] = 0.f;

    int r0i = tid >> 2,         c80 = (tid & 3) * 8;
    int r1i = (tid + 256) >> 2;

    auto issue = [&](int kt) {
        uint32_t st = sbase + (uint32_t)(kt % NSTG) * STAGE_ELEMS * 2;
#pragma unroll
        for (int h = 0; h < 2; ++h) {
            int row = h ? r1i : r0i;
            size_t ga = (size_t)(m0 + row) * 512 + kt * 32 + c80;
            size_t gb = (size_t)(n0 + row) * 512 + kt * 32 + c80;
            uint32_t so = (uint32_t)(row * LDS + c80) * 2;
            cp16(st + 0 * ARR_ELEMS * 2 + so, A + ga);
            cp16(st + 1 * ARR_ELEMS * 2 + so, Wh + gb);
        }
    };

    issue(0); CP_COMMIT();
    issue(1); CP_COMMIT();

    for (int kt = 0; kt < 16; ++kt) {
        if (kt < 14) {
            issue(kt + 2);
            CP_COMMIT();
            CP_WAIT(2);
        } else if (kt == 14) {
            CP_WAIT(1);
        } else {
            CP_WAIT(0);
        }
        __syncthreads();

        uint32_t st = sbase + (uint32_t)(kt % NSTG) * STAGE_ELEMS * 2;
        uint32_t arowA = (uint32_t)((wm * 64 + (lane & 15)) * LDS) * 2;
        uint32_t acolA = (uint32_t)((lane >> 4) * 8) * 2;
        uint32_t browB = (uint32_t)((wn * 32 + (lane & 7)) * LDS) * 2;
        uint32_t bcolB = (uint32_t)(((lane >> 3) & 1) * 8) * 2;

#pragma unroll
        for (int ks = 0; ks < 2; ++ks) {
            uint32_t ah[4][4], bh[4][2];
            uint32_t kofs = (uint32_t)(ks * 16) * 2;
#pragma unroll
            for (int mt = 0; mt < 4; ++mt)
                ldsm_x4(ah[mt], st + arowA + (uint32_t)(mt * 16 * LDS) * 2 + acolA + kofs);
#pragma unroll
            for (int nt = 0; nt < 4; ++nt)
                ldsm_x2(bh[nt], st + ARR_ELEMS * 2 + browB + (uint32_t)(nt * 8 * LDS) * 2 + bcolB + kofs);
#pragma unroll
            for (int mt = 0; mt < 4; ++mt)
#pragma unroll
                for (int nt = 0; nt < 4; ++nt)
                    mma16816(acc[mt][nt], ah[mt][0], ah[mt][1], ah[mt][2], ah[mt][3], bh[nt][0], bh[nt][1]);
        }
        __syncthreads();
    }

    /* ---------------- epilogue ---------------- */
#pragma unroll
    for (int nt = 0; nt < 4; ++nt) {
        int col = n0 + wn * 32 + nt * 8 + (lane & 3) * 2;
        float bv0 = __ldg(bias + col);
        float bv1 = __ldg(bias + col + 1);
#pragma unroll
        for (int mt = 0; mt < 4; ++mt) {
            int row = m0 + wm * 64 + mt * 16 + (lane >> 2);
#pragma unroll
            for (int half = 0; half < 2; ++half) {
                int r = row + half * 8;
                float v0 = acc[mt][nt][half * 2 + 0] + bv0;
                float v1 = acc[mt][nt][half * 2 + 1] + bv1;
                size_t go = (size_t)r * 512 + col;
                if (LAST) {
                    if (r < NCTX) {    /* context: transposed fp16 for cov/xty */
                        int b = r >> 10, n = r & 1023;
                        size_t o0 = ((size_t)b * NP + col) * 1024 + n;
                        g_PT[o0]        = __float2half_rn(v0);
                        g_PT[o0 + 1024] = __float2half_rn(v1);
                    } else {           /* target: fp32 for predict */
                        *(float2*)(Of + go) = make_float2(v0, v1);
                    }
                } else {
                    if (SIN) { v0 = sin_poly(v0); v1 = sin_poly(v1); }  /* args << pi/2 */
                    __half h0 = __float2half_rn(v0);
                    __half h1 = __float2half_rn(v1);
                    uint32_t uh = ((uint32_t)__half_as_ushort(h1) << 16) | __half_as_ushort(h0);
                    *(uint32_t*)(O + go) = uh;
                }
            }
        }
    }
}

/* ---------------- per-batch stats (mean/std) + xty from fp16 PT ------- */
__device__ __forceinline__ float block_reduce_512(float v, float* red, int tid) {
    red[tid] = v; __syncthreads();
    for (int s = 256; s > 0; s >>= 1) {
        if (tid < s) red[tid] += red[tid + s];
        __syncthreads();
    }
    float r = red[0];
    __syncthreads();
    return r;
}

__global__ void __launch_bounds__(512) stats_xty_kernel(const float* __restrict__ y) {
    int b = blockIdx.x;
    int tid = threadIdx.x;
    __shared__ float yc[1024];
    __shared__ float red[512];

    float y0 = y[b * 1024 + tid];
    float y1 = y[b * 1024 + 512 + tid];
    float sum   = block_reduce_512(y0 + y1, red, tid);
    float sumsq = block_reduce_512(y0 * y0 + y1 * y1, red, tid);

    float mean = sum / 1024.0f;
    float var  = (sumsq - sum * sum / 1024.0f) / 1023.0f;
    float stdv = sqrtf(var);
    float inv  = 1.0f / stdv;
    yc[tid]       = (y0 - mean) * inv;
    yc[tid + 512] = (y1 - mean) * inv;
    if (tid == 0) { g_stats[b * 2] = mean; g_stats[b * 2 + 1] = stdv; }
    __syncthreads();

    float sy = block_reduce_512(yc[tid] + yc[tid + 512], red, tid);

    const __half* Pb = g_PT + (size_t)b * NP * 1024;
    int warp = tid >> 5, lane = tid & 31;
    for (int r = warp; r < 512; r += 16) {
        const __half* rowp = Pb + (size_t)r * 1024;
        float acc = 0.f;
#pragma unroll 4
        for (int n = lane * 2; n < 1024; n += 64) {
            __half2 h2 = *(const __half2*)(rowp + n);
            float2 f = __half22float2(h2);
            acc = fmaf(f.x, yc[n], acc);
            acc = fmaf(f.y, yc[n + 1], acc);
        }
#pragma unroll
        for (int o = 16; o > 0; o >>= 1) acc += __shfl_down_sync(0xffffffffu, acc, o);
        if (lane == 0) g_xty[b * NP + r] = acc;
    }
    if (tid == 0) g_xty[b * NP + 512] = sy;
    if (tid < NP - 513) g_xty[b * NP + 513 + tid] = 0.0f;
}

/* -------- cov = PhiT PhiT^T + noise*I via fp16 HMMA ------------------- */
#define CLDS 40
#define CARR (64*CLDS)
#define CSTAGE (2*CARR)

__global__ void __launch_bounds__(256, 2) cov_mma(const float* __restrict__ log_noise) {
    __shared__ __half sm[NSTG * CSTAGE];
    int b = blockIdx.y;
    int t = blockIdx.x;
    int ti = 0;
    while ((ti + 1) * (ti + 2) / 2 <= t) ti++;
    int tj = t - ti * (ti + 1) / 2;
    int r0 = ti * 64, s0 = tj * 64;

    const __half* Ph = g_PT + (size_t)b * NP * 1024;

    int tid = threadIdx.x, lane = tid & 31, wid = tid >> 5;
    int wm = wid >> 2, wn = wid & 3;
    uint32_t sbase = smem_u32(sm);

    float acc[2][2][4];
#pragma unroll
    for (int a = 0; a < 2; a++)
#pragma unroll
        for (int c = 0; c < 2; c++)
#pragma unroll
            for (int d = 0; d < 4; d++) acc[a][c][d] = 0.f;

    int lrow = tid >> 2, lc8 = (tid & 3) * 8;

    auto issue = [&](int kt) {
        uint32_t st = sbase + (uint32_t)(kt % NSTG) * CSTAGE * 2;
        size_t ga = (size_t)(r0 + lrow) * 1024 + kt * 32 + lc8;
        size_t gb = (size_t)(s0 + lrow) * 1024 + kt * 32 + lc8;
        uint32_t so = (uint32_t)(lrow * CLDS + lc8) * 2;
        cp16(st + 0 * CARR * 2 + so, Ph + ga);
        cp16(st + 1 * CARR * 2 + so, Ph + gb);
    };

    issue(0); CP_COMMIT();
    issue(1); CP_COMMIT();

    for (int kt = 0; kt < 32; ++kt) {
        if (kt < 30) {
            issue(kt + 2);
            CP_COMMIT();
            CP_WAIT(2);
        } else if (kt == 30) {
            CP_WAIT(1);
        } else {
            CP_WAIT(0);
        }
        __syncthreads();

        uint32_t st = sbase + (uint32_t)(kt % NSTG) * CSTAGE * 2;
        uint32_t arow = (uint32_t)((wm * 32 + (lane & 15)) * CLDS) * 2;
        uint32_t acol = (uint32_t)((lane >> 4) * 8) * 2;
        uint32_t brow = (uint32_t)((wn * 16 + (lane & 7)) * CLDS) * 2;
        uint32_t bcol = (uint32_t)(((lane >> 3) & 1) * 8) * 2;

#pragma unroll
        for (int ks = 0; ks < 2; ++ks) {
            uint32_t ah[2][4], bh[2][2];
            uint32_t kofs = (uint32_t)(ks * 16) * 2;
#pragma unroll
            for (int mt = 0; mt < 2; ++mt)
                ldsm_x4(ah[mt], st + arow + (uint32_t)(mt * 16 * CLDS) * 2 + acol + kofs);
#pragma unroll
            for (int nt = 0; nt < 2; ++nt)
                ldsm_x2(bh[nt], st + CARR * 2 + brow + (uint32_t)(nt * 8 * CLDS) * 2 + bcol + kofs);
#pragma unroll
            for (int mt = 0; mt < 2; ++mt)
#pragma unroll
                for (int nt = 0; nt < 2; ++nt)
                    mma16816(acc[mt][nt], ah[mt][0], ah[mt][1], ah[mt][2], ah[mt][3], bh[nt][0], bh[nt][1]);
        }
        __syncthreads();
    }

    float noise = expf(log_noise[0]);
    float* Cv = g_cov + (size_t)b * NP * NP;
#pragma unroll
    for (int nt = 0; nt < 2; ++nt) {
        int c = s0 + wn * 16 + nt * 8 + (lane & 3) * 2;
#pragma unroll
        for (int mt = 0; mt < 2; ++mt) {
            int rb = r0 + wm * 32 + mt * 16 + (lane >> 2);
#pragma unroll
            for (int half = 0; half < 2; ++half) {
                int r = rb + half * 8;
                float v0 = acc[mt][nt][half * 2 + 0];
                float v1 = acc[mt][nt][half * 2 + 1];
                if (r == c)     v0 = (r <= 512) ? v0 + noise : 1.0f;
                if (r == c + 1) v1 = (r <= 512) ? v1 + noise : 1.0f;
                Cv[(size_t)r * NP + c]     = v0;
                Cv[(size_t)r * NP + c + 1] = v1;
            }
        }
    }
}

/* --------- blocked Cholesky, HMMA trailing update (split fp16) -------- */
#define PLDS 40
#define PAN_ELEMS (544*PLDS)
#define CHOL_SMEM (PAN_ELEMS*2*2 + 32*33*4)   /* 91264 bytes */

__global__ void __launch_bounds__(256, 1) cholesky_kernel() {
    extern __shared__ char csm[];
    __half* panH = (__half*)csm;
    __half* panL = panH + PAN_ELEMS;
    float (*Ad)[33] = (float(*)[33])(csm + PAN_ELEMS * 2 * 2);
    uint32_t pHb = smem_u32(panH);
    uint32_t pLb = smem_u32(panL);

    float* A = g_cov + (size_t)blockIdx.x * NP * NP;
    int tid = threadIdx.x, lane = tid & 31, wid = tid >> 5;

    for (int p = 0; p < NP / NB; ++p) {
        int j0 = p * NB;
        int m = NP - j0 - NB;

        for (int e = tid; e < NB * NB; e += 256) {
            int r = e >> 5, c = e & 31;
            Ad[r][c] = A[(size_t)(j0 + r) * NP + j0 + c];
        }
        __syncthreads();
        if (tid < 32) {
            for (int j = 0; j < NB; ++j) {
                if (lane == j) Ad[j][j] = sqrtf(Ad[j][j]);
                __syncwarp();
                float d = Ad[j][j];
                if (lane > j) Ad[lane][j] /= d;
                __syncwarp();
                if (lane > j) {
                    float lij = Ad[lane][j];
                    for (int k = j + 1; k <= lane; ++k)
                        Ad[lane][k] -= lij * Ad[k][j];
                }
                __syncwarp();
            }
        }
        __syncthreads();
        for (int e = tid; e < NB * NB; e += 256) {
            int r = e >> 5, c = e & 31;
            A[(size_t)(j0 + r) * NP + j0 + c] = Ad[r][c];
        }

        for (int i = j0 + NB + tid; i < NP; i += 256) {
            float x[NB];
            float* arow = &A[(size_t)i * NP + j0];
#pragma unroll
            for (int j = 0; j < NB; ++j) x[j] = arow[j];
#pragma unroll
            for (int j = 0; j < NB; ++j) {
                float s = x[j];
#pragma unroll
                for (int k = 0; k < NB; ++k)
                    if (k < j) s -= x[k] * Ad[j][k];
                x[j] = s / Ad[j][j];
            }
            int pr = i - j0 - NB;
#pragma unroll
            for (int j = 0; j < NB; ++j) {
                arow[j] = x[j];
                __half h = __float2half_rn(x[j]);
                panH[pr * PLDS + j] = h;
                panL[pr * PLDS + j] = __float2half_rn(x[j] - __half2float(h));
            }
        }
        __syncthreads();

        if (m > 0) {
            int T = m >> 5;
            int base = j0 + NB;
            int pi = 0;
            for (int ti = 0; ti < T; ++ti) {
                for (int tk = 0; tk <= ti; ++tk, ++pi) {
                    if ((pi & 7) != wid) continue;
                    float acc[2][4][4];
#pragma unroll
                    for (int a = 0; a < 2; a++)
#pragma unroll
                        for (int b2 = 0; b2 < 4; b2++)
#pragma unroll
                            for (int c = 0; c < 4; c++) acc[a][b2][c] = 0.f;

#pragma unroll
                    for (int pass = 0; pass < 2; ++pass) {
                        uint32_t ab = pass ? pLb : pHb;
#pragma unroll
                        for (int ks = 0; ks < 2; ++ks) {
                            uint32_t kofs = (uint32_t)(ks * 16) * 2;
                            uint32_t ah[2][4], bh[4][2];
#pragma unroll
                            for (int mt = 0; mt < 2; ++mt) {
                                uint32_t row = (uint32_t)(ti * 32 + mt * 16 + (lane & 15));
                                ldsm_x4(ah[mt], ab + (row * PLDS) * 2 + (uint32_t)((lane >> 4) * 8) * 2 + kofs);
                            }
#pragma unroll
                            for (int nt = 0; nt < 4; ++nt) {
                                uint32_t row = (uint32_t)(tk * 32 + nt * 8 + (lane & 7));
                                ldsm_x2(bh[nt], pHb + (row * PLDS) * 2 + (uint32_t)(((lane >> 3) & 1) * 8) * 2 + kofs);
                            }
#pragma unroll
                            for (int mt = 0; mt < 2; ++mt)
#pragma unroll
                                for (int nt = 0; nt < 4; ++nt)
                                    mma16816(acc[mt][nt], ah[mt][0], ah[mt][1], ah[mt][2], ah[mt][3],
                                             bh[nt][0], bh[nt][1]);
                        }
                    }
#pragma unroll
                    for (int mt = 0; mt < 2; ++mt) {
#pragma unroll
                        for (int half = 0; half < 2; ++half) {
                            int gr = base + ti * 32 + mt * 16 + (lane >> 2) + half * 8;
#pragma unroll
                            for (int nt = 0; nt < 4; ++nt) {
                                int gc = base + tk * 32 + nt * 8 + (lane & 3) * 2;
                                float u0 = acc[mt][nt][half * 2 + 0];
                                float u1 = acc[mt][nt][half * 2 + 1];
                                if (ti != tk || gc <= gr)
                                    A[(size_t)gr * NP + gc] -= u0;
                                if (ti != tk || gc + 1 <= gr)
                                    A[(size_t)gr * NP + gc + 1] -= u1;
                            }
                        }
                    }
                }
            }
        }
        __syncthreads();
    }
}

/* ---------------- forward + backward triangular solves ---------------- */
__global__ void __launch_bounds__(256) solve_kernel() {
    int b = blockIdx.x;
    const float* A = g_cov + (size_t)b * NP * NP;
    int tid = threadIdx.x;
    __shared__ float z[NP];
    __shared__ float Ad[NB][NB + 1];

    for (int i = tid; i < NP; i += 256) z[i] = g_xty[b * NP + i];
    __syncthreads();

    for (int p = 0; p < NP / NB; ++p) {
        int j0 = p * NB;
        for (int e = tid; e < NB * NB; e += 256) {
            int r = e / NB, c = e % NB;
            Ad[r][c] = A[(size_t)(j0 + r) * NP + j0 + c];
        }
        __syncthreads();
        if (tid < 32) {
            int lane = tid;
            float v = z[j0 + lane];
            for (int j = 0; j < NB; ++j) {
                if (lane == j) v /= Ad[j][j];
                float zj = __shfl_sync(0xffffffffu, v, j);
                if (lane > j) v -= Ad[lane][j] * zj;
            }
            z[j0 + lane] = v;
        }
        __syncthreads();
        for (int i = j0 + NB + tid; i < NP; i += 256) {
            float s = 0.f;
            const float* arow = &A[(size_t)i * NP + j0];
#pragma unroll
            for (int k = 0; k < NB; ++k) s = fmaf(arow[k], z[j0 + k], s);
            z[i] -= s;
        }
        __syncthreads();
    }

    for (int p = NP / NB - 1; p >= 0; --p) {
        int j0 = p * NB;
        for (int e = tid; e < NB * NB; e += 256) {
            int r = e / NB, c = e % NB;
            Ad[r][c] = A[(size_t)(j0 + r) * NP + j0 + c];
        }
        __syncthreads();
        if (tid < 32) {
            int lane = tid;
            float v = z[j0 + lane];
            for (int j = NB - 1; j >= 0; --j) {
                if (lane == j) v /= Ad[j][j];
                float wj = __shfl_sync(0xffffffffu, v, j);
                if (lane < j) v -= Ad[j][lane] * wj;
            }
            z[j0 + lane] = v;
        }
        __syncthreads();
        for (int i = tid; i < j0; i += 256) {
            float s = 0.f;
#pragma unroll
            for (int k = 0; k < NB; ++k)
                s = fmaf(A[(size_t)(j0 + k) * NP + i], z[j0 + k], s);
            z[i] -= s;
        }
        __syncthreads();
    }

    for (int i = tid; i < NP; i += 256) g_w[b * NP + i] = z[i];
}

/* ---------------- prediction: y = (tr @ w) * std + mean --------------- */
__global__ void __launch_bounds__(256) predict_kernel(float* __restrict__ out) {
    int warp = threadIdx.x >> 5, lane = threadIdx.x & 31;
    int row = blockIdx.x * 8 + warp;
    int b = row >> 10;
    __shared__ float ws[NP];
    for (int i = threadIdx.x; i < NP; i += 256) ws[i] = g_w[b * NP + i];
    __syncthreads();

    const float* f = g_bufF + ((size_t)NCTX + row) * 512;
    float s = 0.f;
    for (int c = lane * 4; c < 512; c += 128) {
        float4 v = *(const float4*)&f[c];
        s += v.x * ws[c] + v.y * ws[c + 1] + v.z * ws[c + 2] + v.w * ws[c + 3];
    }
#pragma unroll
    for (int o = 16; o > 0; o >>= 1) s += __shfl_down_sync(0xffffffffu, s, o);
    if (lane == 0) {
        s += ws[512];
        float mean = g_stats[b * 2], stdv = g_stats[b * 2 + 1];
        out[row] = s * stdv + mean;
    }
}

/* ---------------------------- launcher -------------------------------- */
extern "C" void kernel_launch(void* const* d_in, const int* in_sizes, int n_in,
                              void* d_out, int out_size) {
    const float* xc  = (const float*)d_in[0];
    const float* y   = (const float*)d_in[1];
    const float* xt  = (const float*)d_in[2];
    const float* W0  = (const float*)d_in[3];
    const float* b0  = (const float*)d_in[4];
    const float* W1  = (const float*)d_in[5];
    const float* b1  = (const float*)d_in[6];
    const float* W2  = (const float*)d_in[7];
    const float* b2  = (const float*)d_in[8];
    const float* Wr  = (const float*)d_in[9];
    const float* br  = (const float*)d_in[10];
    const float* lnv = (const float*)d_in[11];
    float* out = (float*)d_out;
    (void)in_sizes; (void)n_in; (void)out_size;

    cudaFuncSetAttribute(mma_gemm<true, false>,
                         cudaFuncAttributeMaxDynamicSharedMemorySize, GEMM_SMEM);
    cudaFuncSetAttribute(mma_gemm<false, true>,
                         cudaFuncAttributeMaxDynamicSharedMemorySize, GEMM_SMEM);
    cudaFuncSetAttribute(cholesky_kernel,
                         cudaFuncAttributeMaxDynamicSharedMemorySize, CHOL_SMEM);

    __half *hA, *hB, *w1h, *w2h, *wrh;
    float* bufF;
    cudaGetSymbolAddress((void**)&hA, g_hA);
    cudaGetSymbolAddress((void**)&hB, g_hB);
    cudaGetSymbolAddress((void**)&w1h, g_W1h);
    cudaGetSymbolAddress((void**)&w2h, g_W2h);
    cudaGetSymbolAddress((void**)&wrh, g_Wrh);
    cudaGetSymbolAddress((void**)&bufF, g_bufF);

    prep_w_kernel<<<1024, 256>>>(W1, W2, Wr);
    pt_init_kernel<<<16384, 256>>>();
    layer0_kernel<<<(NPTS * 512) / 256, 256>>>(xc, xt, W0, b0);

    dim3 ggrid(4, NPTS / 128);
    mma_gemm<true, false><<<ggrid, 256, GEMM_SMEM>>>(hA, w1h, b1, hB, nullptr);
    mma_gemm<true, false><<<ggrid, 256, GEMM_SMEM>>>(hB, w2h, b2, hA, nullptr);
    mma_gemm<false, true><<<ggrid, 256, GEMM_SMEM>>>(hA, wrh, br, nullptr, bufF);

    stats_xty_kernel<<<BATCH, 512>>>(y);
    dim3 cgrid(45, BATCH);
    cov_mma<<<cgrid, 256>>>(lnv);
    cholesky_kernel<<<BATCH, 256, CHOL_SMEM>>>();
    solve_kernel<<<BATCH, 256>>>();
    predict_kernel<<<NCTX / 8, 256>>>(out);
}

// round 15
// speedup vs baseline: 1.4142x; 1.4142x over previous
#include <cuda_runtime.h>
#include <cuda_fp16.h>
#include <math.h>
#include <stdint.h>

#define BATCH 64
#define NCC   1024
#define NTT   1024
#define HID   512
#define NPTS  (BATCH*(NCC+NTT))   /* 131072 */
#define NCTX  (BATCH*NCC)         /* 65536  */
#define NP    576                 /* padded 513 -> 576 = 18*32 */
#define NB    32

/* ------------------- global scratch (static, no allocs) --------------- */
__device__ __half g_hA[(size_t)NPTS*HID];
__device__ __half g_hB[(size_t)NPTS*HID];
__device__ float  g_bufF[(size_t)NPTS*HID];    /* fp32 target features */
__device__ __half g_PT[(size_t)BATCH*NP*NCC];  /* PhiT [b][r][n]       */
__device__ __half g_W1h[HID*HID];
__device__ __half g_W2h[HID*HID];
__device__ __half g_Wrh[HID*HID];
__device__ float g_cov [(size_t)BATCH*NP*NP];
__device__ float g_xty [BATCH*NP];
__device__ float g_w   [BATCH*NP];
__device__ float g_stats[BATCH*2];

/* ----------------------- PTX helpers (sm_80-era only) ----------------- */
__device__ __forceinline__ uint32_t smem_u32(const void* p) {
    uint32_t a;
    asm("{ .reg .u64 t; cvta.to.shared.u64 t, %1; cvt.u32.u64 %0, t; }" : "=r"(a) : "l"(p));
    return a;
}

__device__ __forceinline__ void cp16(uint32_t dst, const void* src) {
    asm volatile("cp.async.cg.shared.global [%0], [%1], 16;" :: "r"(dst), "l"(src));
}
#define CP_COMMIT() asm volatile("cp.async.commit_group;" ::: "memory")
#define CP_WAIT(n)  asm volatile("cp.async.wait_group %0;" :: "n"(n) : "memory")

__device__ __forceinline__ void ldsm_x4(uint32_t* r, uint32_t addr) {
    asm volatile("ldmatrix.sync.aligned.m8n8.x4.shared.b16 {%0,%1,%2,%3}, [%4];"
        : "=r"(r[0]), "=r"(r[1]), "=r"(r[2]), "=r"(r[3]) : "r"(addr));
}
__device__ __forceinline__ void ldsm_x2(uint32_t* r, uint32_t addr) {
    asm volatile("ldmatrix.sync.aligned.m8n8.x2.shared.b16 {%0,%1}, [%2];"
        : "=r"(r[0]), "=r"(r[1]) : "r"(addr));
}

__device__ __forceinline__ void mma16816(float* c,
        uint32_t a0, uint32_t a1, uint32_t a2, uint32_t a3,
        uint32_t b0, uint32_t b1) {
    asm volatile(
        "mma.sync.aligned.m16n8k16.row.col.f32.f16.f16.f32 "
        "{%0,%1,%2,%3}, {%4,%5,%6,%7}, {%8,%9}, {%0,%1,%2,%3};"
        : "+f"(c[0]), "+f"(c[1]), "+f"(c[2]), "+f"(c[3])
        : "r"(a0), "r"(a1), "r"(a2), "r"(a3), "r"(b0), "r"(b1));
}

/* polynomial sine, valid |x| <= ~2 (Taylor deg-9) — pure FMA, no MUFU */
__device__ __forceinline__ float sin_poly(float x) {
    float x2 = x * x;
    float p = fmaf(x2, 2.75573192e-6f, -1.98412698e-4f);
    p = fmaf(x2, p, 8.33333333e-3f);
    p = fmaf(x2, p, -1.66666667e-1f);
    return fmaf(x * x2, p, x);
}

/* accurate fp32 sin for |arg| up to ~1000: Cody-Waite mod pi + poly */
__device__ __forceinline__ float sin_cw(float arg) {
    float k = rintf(arg * 0.3183098861837907f);
    float r = fmaf(-k, 3.14159274101257324e+0f, arg);
    r = fmaf(-k, -8.74227765734758577e-8f, r);
    float s = sin_poly(r);
    int ki = (int)k;
    return (ki & 1) ? -s : s;
}

/* ---------------- layer 0: h0 = sin(30*(x*W0 + b0)) ------------------- */
__global__ void layer0_kernel(const float* __restrict__ xc,
                              const float* __restrict__ xt,
                              const float* __restrict__ W0,
                              const float* __restrict__ b0) {
    size_t idx = (size_t)blockIdx.x * blockDim.x + threadIdx.x;
    int p = (int)(idx >> 9);
    int j = (int)(idx & 511);
    float x = (p < NCTX) ? xc[p] : xt[p - NCTX];
    float arg = 30.0f * fmaf(x, W0[j], b0[j]);
    g_hA[idx] = __float2half_rn(sin_cw(arg));
}

/* ------------- weight prep: transpose all 3 weights to fp16 ----------- */
__global__ void prep_w_kernel(const float* __restrict__ W1,
                              const float* __restrict__ W2,
                              const float* __restrict__ Wr) {
    int i = blockIdx.x * 256 + threadIdx.x;
    int k = i >> 9, n = i & 511;
    g_W1h[n * 512 + k] = __float2half_rn(W1[i]);
    g_W2h[n * 512 + k] = __float2half_rn(W2[i]);
    g_Wrh[n * 512 + k] = __float2half_rn(Wr[i]);
}

/* ---- init PhiT rows 512..575: row 512 = ones, rest zero -------------- */
__global__ void pt_init_kernel() {
    int i = blockIdx.x * 256 + threadIdx.x;
    int n   = i & 1023;
    int row = (i >> 10) & 63;
    int b   = i >> 16;
    size_t o = ((size_t)b * NP + 512 + row) * 1024 + n;
    g_PT[o] = __float2half_rn(row == 0 ? 1.0f : 0.0f);
}

/* -------- HMMA fp16 GEMM: C = act(A @ W + bias) ----------------------- */
#define LDS 40
#define ARR_ELEMS (128*LDS)
#define STAGE_ELEMS (2*ARR_ELEMS)
#define NSTG 3
#define GEMM_SMEM (NSTG*STAGE_ELEMS*2)

template<bool SIN, bool LAST>
__global__ void __launch_bounds__(256, 2) mma_gemm(
    const __half* __restrict__ A,
    const __half* __restrict__ Wh,
    const float* __restrict__ bias,
    __half* __restrict__ O,
    float* __restrict__ Of)
{
    extern __shared__ __half sm[];
    int tid = threadIdx.x;
    int lane = tid & 31, wid = tid >> 5;
    int wm = wid >> 2, wn = wid & 3;
    int m0 = blockIdx.y * 128;
    int n0 = blockIdx.x * 128;

    uint32_t sbase = smem_u32(sm);

    float acc[4][4][4];
#pragma unroll
    for (int a = 0; a < 4; a++)
#pragma unroll
        for (int b = 0; b < 4; b++)
#pragma unroll
            for (int c = 0; c < 4; c++) acc[a][b][c] = 0.f;

    int r0i = tid >> 2,         c80 = (tid & 3) * 8;
    int r1i = (tid + 256) >> 2;

    auto issue = [&](int kt) {
        uint32_t st = sbase + (uint32_t)(kt % NSTG) * STAGE_ELEMS * 2;
#pragma unroll
        for (int h = 0; h < 2; ++h) {
            int row = h ? r1i : r0i;
            size_t ga = (size_t)(m0 + row) * 512 + kt * 32 + c80;
            size_t gb = (size_t)(n0 + row) * 512 + kt * 32 + c80;
            uint32_t so = (uint32_t)(row * LDS + c80) * 2;
            cp16(st + 0 * ARR_ELEMS * 2 + so, A + ga);
            cp16(st + 1 * ARR_ELEMS * 2 + so, Wh + gb);
        }
    };

    issue(0); CP_COMMIT();
    issue(1); CP_COMMIT();

    for (int kt = 0; kt < 16; ++kt) {
        if (kt < 14) {
            issue(kt + 2);
            CP_COMMIT();
            CP_WAIT(2);
        } else if (kt == 14) {
            CP_WAIT(1);
        } else {
            CP_WAIT(0);
        }
        __syncthreads();

        uint32_t st = sbase + (uint32_t)(kt % NSTG) * STAGE_ELEMS * 2;
        uint32_t arowA = (uint32_t)((wm * 64 + (lane & 15)) * LDS) * 2;
        uint32_t acolA = (uint32_t)((lane >> 4) * 8) * 2;
        uint32_t browB = (uint32_t)((wn * 32 + (lane & 7)) * LDS) * 2;
        uint32_t bcolB = (uint32_t)(((lane >> 3) & 1) * 8) * 2;

#pragma unroll
        for (int ks = 0; ks < 2; ++ks) {
            uint32_t ah[4][4], bh[4][2];
            uint32_t kofs = (uint32_t)(ks * 16) * 2;
#pragma unroll
            for (int mt = 0; mt < 4; ++mt)
                ldsm_x4(ah[mt], st + arowA + (uint32_t)(mt * 16 * LDS) * 2 + acolA + kofs);
#pragma unroll
            for (int nt = 0; nt < 4; ++nt)
                ldsm_x2(bh[nt], st + ARR_ELEMS * 2 + browB + (uint32_t)(nt * 8 * LDS) * 2 + bcolB + kofs);
#pragma unroll
            for (int mt = 0; mt < 4; ++mt)
#pragma unroll
                for (int nt = 0; nt < 4; ++nt)
                    mma16816(acc[mt][nt], ah[mt][0], ah[mt][1], ah[mt][2], ah[mt][3], bh[nt][0], bh[nt][1]);
        }
        __syncthreads();
    }

    /* ---------------- epilogue ---------------- */
#pragma unroll
    for (int nt = 0; nt < 4; ++nt) {
        int col = n0 + wn * 32 + nt * 8 + (lane & 3) * 2;
        float bv0 = __ldg(bias + col);
        float bv1 = __ldg(bias + col + 1);
#pragma unroll
        for (int mt = 0; mt < 4; ++mt) {
            int row = m0 + wm * 64 + mt * 16 + (lane >> 2);
#pragma unroll
            for (int half = 0; half < 2; ++half) {
                int r = row + half * 8;
                float v0 = acc[mt][nt][half * 2 + 0] + bv0;
                float v1 = acc[mt][nt][half * 2 + 1] + bv1;
                size_t go = (size_t)r * 512 + col;
                if (LAST) {
                    if (r < NCTX) {    /* context: transposed fp16 for cov/xty */
                        int b = r >> 10, n = r & 1023;
                        size_t o0 = ((size_t)b * NP + col) * 1024 + n;
                        g_PT[o0]        = __float2half_rn(v0);
                        g_PT[o0 + 1024] = __float2half_rn(v1);
                    } else {           /* target: fp32 for predict */
                        *(float2*)(Of + go) = make_float2(v0, v1);
                    }
                } else {
                    if (SIN) { v0 = sin_poly(v0); v1 = sin_poly(v1); }
                    __half h0 = __float2half_rn(v0);
                    __half h1 = __float2half_rn(v1);
                    uint32_t uh = ((uint32_t)__half_as_ushort(h1) << 16) | __half_as_ushort(h0);
                    *(uint32_t*)(O + go) = uh;
                }
            }
        }
    }
}

/* ---------------- per-batch stats (mean/std) + xty from fp16 PT ------- */
__device__ __forceinline__ float block_reduce_512(float v, float* red, int tid) {
    red[tid] = v; __syncthreads();
    for (int s = 256; s > 0; s >>= 1) {
        if (tid < s) red[tid] += red[tid + s];
        __syncthreads();
    }
    float r = red[0];
    __syncthreads();
    return r;
}

__global__ void __launch_bounds__(512) stats_xty_kernel(const float* __restrict__ y) {
    int b = blockIdx.x;
    int tid = threadIdx.x;
    __shared__ float yc[1024];
    __shared__ float red[512];

    float y0 = y[b * 1024 + tid];
    float y1 = y[b * 1024 + 512 + tid];
    float sum   = block_reduce_512(y0 + y1, red, tid);
    float sumsq = block_reduce_512(y0 * y0 + y1 * y1, red, tid);

    float mean = sum / 1024.0f;
    float var  = (sumsq - sum * sum / 1024.0f) / 1023.0f;
    float stdv = sqrtf(var);
    float inv  = 1.0f / stdv;
    yc[tid]       = (y0 - mean) * inv;
    yc[tid + 512] = (y1 - mean) * inv;
    if (tid == 0) { g_stats[b * 2] = mean; g_stats[b * 2 + 1] = stdv; }
    __syncthreads();

    float sy = block_reduce_512(yc[tid] + yc[tid + 512], red, tid);

    const __half* Pb = g_PT + (size_t)b * NP * 1024;
    int warp = tid >> 5, lane = tid & 31;
    for (int r = warp; r < 512; r += 16) {
        const __half* rowp = Pb + (size_t)r * 1024;
        float acc = 0.f;
#pragma unroll 4
        for (int n = lane * 2; n < 1024; n += 64) {
            __half2 h2 = *(const __half2*)(rowp + n);
            float2 f = __half22float2(h2);
            acc = fmaf(f.x, yc[n], acc);
            acc = fmaf(f.y, yc[n + 1], acc);
        }
#pragma unroll
        for (int o = 16; o > 0; o >>= 1) acc += __shfl_down_sync(0xffffffffu, acc, o);
        if (lane == 0) g_xty[b * NP + r] = acc;
    }
    if (tid == 0) g_xty[b * NP + 512] = sy;
    if (tid < NP - 513) g_xty[b * NP + 513 + tid] = 0.0f;
}

/* -------- cov = PhiT PhiT^T + noise*I via fp16 HMMA ------------------- */
#define CLDS 40
#define CARR (64*CLDS)
#define CSTAGE (2*CARR)

__global__ void __launch_bounds__(256, 2) cov_mma(const float* __restrict__ log_noise) {
    __shared__ __half sm[NSTG * CSTAGE];
    int b = blockIdx.y;
    int t = blockIdx.x;
    int ti = 0;
    while ((ti + 1) * (ti + 2) / 2 <= t) ti++;
    int tj = t - ti * (ti + 1) / 2;
    int r0 = ti * 64, s0 = tj * 64;

    const __half* Ph = g_PT + (size_t)b * NP * 1024;

    int tid = threadIdx.x, lane = tid & 31, wid = tid >> 5;
    int wm = wid >> 2, wn = wid & 3;
    uint32_t sbase = smem_u32(sm);

    float acc[2][2][4];
#pragma unroll
    for (int a = 0; a < 2; a++)
#pragma unroll
        for (int c = 0; c < 2; c++)
#pragma unroll
            for (int d = 0; d < 4; d++) acc[a][c][d] = 0.f;

    int lrow = tid >> 2, lc8 = (tid & 3) * 8;

    auto issue = [&](int kt) {
        uint32_t st = sbase + (uint32_t)(kt % NSTG) * CSTAGE * 2;
        size_t ga = (size_t)(r0 + lrow) * 1024 + kt * 32 + lc8;
        size_t gb = (size_t)(s0 + lrow) * 1024 + kt * 32 + lc8;
        uint32_t so = (uint32_t)(lrow * CLDS + lc8) * 2;
        cp16(st + 0 * CARR * 2 + so, Ph + ga);
        cp16(st + 1 * CARR * 2 + so, Ph + gb);
    };

    issue(0); CP_COMMIT();
    issue(1); CP_COMMIT();

    for (int kt = 0; kt < 32; ++kt) {
        if (kt < 30) {
            issue(kt + 2);
            CP_COMMIT();
            CP_WAIT(2);
        } else if (kt == 30) {
            CP_WAIT(1);
        } else {
            CP_WAIT(0);
        }
        __syncthreads();

        uint32_t st = sbase + (uint32_t)(kt % NSTG) * CSTAGE * 2;
        uint32_t arow = (uint32_t)((wm * 32 + (lane & 15)) * CLDS) * 2;
        uint32_t acol = (uint32_t)((lane >> 4) * 8) * 2;
        uint32_t brow = (uint32_t)((wn * 16 + (lane & 7)) * CLDS) * 2;
        uint32_t bcol = (uint32_t)(((lane >> 3) & 1) * 8) * 2;

#pragma unroll
        for (int ks = 0; ks < 2; ++ks) {
            uint32_t ah[2][4], bh[2][2];
            uint32_t kofs = (uint32_t)(ks * 16) * 2;
#pragma unroll
            for (int mt = 0; mt < 2; ++mt)
                ldsm_x4(ah[mt], st + arow + (uint32_t)(mt * 16 * CLDS) * 2 + acol + kofs);
#pragma unroll
            for (int nt = 0; nt < 2; ++nt)
                ldsm_x2(bh[nt], st + CARR * 2 + brow + (uint32_t)(nt * 8 * CLDS) * 2 + bcol + kofs);
#pragma unroll
            for (int mt = 0; mt < 2; ++mt)
#pragma unroll
                for (int nt = 0; nt < 2; ++nt)
                    mma16816(acc[mt][nt], ah[mt][0], ah[mt][1], ah[mt][2], ah[mt][3], bh[nt][0], bh[nt][1]);
        }
        __syncthreads();
    }

    float noise = expf(log_noise[0]);
    float* Cv = g_cov + (size_t)b * NP * NP;
#pragma unroll
    for (int nt = 0; nt < 2; ++nt) {
        int c = s0 + wn * 16 + nt * 8 + (lane & 3) * 2;
#pragma unroll
        for (int mt = 0; mt < 2; ++mt) {
            int rb = r0 + wm * 32 + mt * 16 + (lane >> 2);
#pragma unroll
            for (int half = 0; half < 2; ++half) {
                int r = rb + half * 8;
                float v0 = acc[mt][nt][half * 2 + 0];
                float v1 = acc[mt][nt][half * 2 + 1];
                if (r == c)     v0 = (r <= 512) ? v0 + noise : 1.0f;
                if (r == c + 1) v1 = (r <= 512) ? v1 + noise : 1.0f;
                Cv[(size_t)r * NP + c]     = v0;
                Cv[(size_t)r * NP + c + 1] = v1;
            }
        }
    }
}

/* --------- blocked Cholesky, HMMA trailing update (split fp16) -------- */
#define PLDS 40
#define PAN_ELEMS (544*PLDS)
#define CHOL_SMEM (PAN_ELEMS*2*2 + 32*33*4)   /* 91264 bytes */

__global__ void __launch_bounds__(256, 1) cholesky_kernel() {
    extern __shared__ char csm[];
    __half* panH = (__half*)csm;
    __half* panL = panH + PAN_ELEMS;
    float (*Ad)[33] = (float(*)[33])(csm + PAN_ELEMS * 2 * 2);
    uint32_t pHb = smem_u32(panH);
    uint32_t pLb = smem_u32(panL);

    float* A = g_cov + (size_t)blockIdx.x * NP * NP;
    int tid = threadIdx.x, lane = tid & 31, wid = tid >> 5;

    for (int p = 0; p < NP / NB; ++p) {
        int j0 = p * NB;
        int m = NP - j0 - NB;

        for (int e = tid; e < NB * NB; e += 256) {
            int r = e >> 5, c = e & 31;
            Ad[r][c] = A[(size_t)(j0 + r) * NP + j0 + c];
        }
        __syncthreads();
        if (tid < 32) {
            for (int j = 0; j < NB; ++j) {
                if (lane == j) Ad[j][j] = sqrtf(Ad[j][j]);
                __syncwarp();
                float d = Ad[j][j];
                if (lane > j) Ad[lane][j] /= d;
                __syncwarp();
                if (lane > j) {
                    float lij = Ad[lane][j];
                    for (int k = j + 1; k <= lane; ++k)
                        Ad[lane][k] -= lij * Ad[k][j];
                }
                __syncwarp();
            }
        }
        __syncthreads();
        for (int e = tid; e < NB * NB; e += 256) {
            int r = e >> 5, c = e & 31;
            A[(size_t)(j0 + r) * NP + j0 + c] = Ad[r][c];
        }

        for (int i = j0 + NB + tid; i < NP; i += 256) {
            float x[NB];
            float* arow = &A[(size_t)i * NP + j0];
#pragma unroll
            for (int j = 0; j < NB; ++j) x[j] = arow[j];
#pragma unroll
            for (int j = 0; j < NB; ++j) {
                float s = x[j];
#pragma unroll
                for (int k = 0; k < NB; ++k)
                    if (k < j) s -= x[k] * Ad[j][k];
                x[j] = s / Ad[j][j];
            }
            int pr = i - j0 - NB;
#pragma unroll
            for (int j = 0; j < NB; ++j) {
                arow[j] = x[j];
                __half h = __float2half_rn(x[j]);
                panH[pr * PLDS + j] = h;
                panL[pr * PLDS + j] = __float2half_rn(x[j] - __half2float(h));
            }
        }
        __syncthreads();

        if (m > 0) {
            int T = m >> 5;
            int base = j0 + NB;
            int pi = 0;
            for (int ti = 0; ti < T; ++ti) {
                for (int tk = 0; tk <= ti; ++tk, ++pi) {
                    if ((pi & 7) != wid) continue;
                    float acc[2][4][4];
#pragma unroll
                    for (int a = 0; a < 2; a++)
#pragma unroll
                        for (int b2 = 0; b2 < 4; b2++)
#pragma unroll
                            for (int c = 0; c < 4; c++) acc[a][b2][c] = 0.f;

#pragma unroll
                    for (int pass = 0; pass < 2; ++pass) {
                        uint32_t ab = pass ? pLb : pHb;
#pragma unroll
                        for (int ks = 0; ks < 2; ++ks) {
                            uint32_t kofs = (uint32_t)(ks * 16) * 2;
                            uint32_t ah[2][4], bh[4][2];
#pragma unroll
                            for (int mt = 0; mt < 2; ++mt) {
                                uint32_t row = (uint32_t)(ti * 32 + mt * 16 + (lane & 15));
                                ldsm_x4(ah[mt], ab + (row * PLDS) * 2 + (uint32_t)((lane >> 4) * 8) * 2 + kofs);
                            }
#pragma unroll
                            for (int nt = 0; nt < 4; ++nt) {
                                uint32_t row = (uint32_t)(tk * 32 + nt * 8 + (lane & 7));
                                ldsm_x2(bh[nt], pHb + (row * PLDS) * 2 + (uint32_t)(((lane >> 3) & 1) * 8) * 2 + kofs);
                            }
#pragma unroll
                            for (int mt = 0; mt < 2; ++mt)
#pragma unroll
                                for (int nt = 0; nt < 4; ++nt)
                                    mma16816(acc[mt][nt], ah[mt][0], ah[mt][1], ah[mt][2], ah[mt][3],
                                             bh[nt][0], bh[nt][1]);
                        }
                    }
#pragma unroll
                    for (int mt = 0; mt < 2; ++mt) {
#pragma unroll
                        for (int half = 0; half < 2; ++half) {
                            int gr = base + ti * 32 + mt * 16 + (lane >> 2) + half * 8;
#pragma unroll
                            for (int nt = 0; nt < 4; ++nt) {
                                int gc = base + tk * 32 + nt * 8 + (lane & 3) * 2;
                                float u0 = acc[mt][nt][half * 2 + 0];
                                float u1 = acc[mt][nt][half * 2 + 1];
                                if (ti != tk || gc <= gr)
                                    A[(size_t)gr * NP + gc] -= u0;
                                if (ti != tk || gc + 1 <= gr)
                                    A[(size_t)gr * NP + gc + 1] -= u1;
                            }
                        }
                    }
                }
            }
        }
        __syncthreads();
    }
}

/* ---------------- forward + backward triangular solves ---------------- */
__global__ void __launch_bounds__(256) solve_kernel() {
    int b = blockIdx.x;
    const float* A = g_cov + (size_t)b * NP * NP;
    int tid = threadIdx.x;
    __shared__ float z[NP];
    __shared__ float Ad[NB][NB + 1];

    for (int i = tid; i < NP; i += 256) z[i] = g_xty[b * NP + i];
    __syncthreads();

    for (int p = 0; p < NP / NB; ++p) {
        int j0 = p * NB;
        for (int e = tid; e < NB * NB; e += 256) {
            int r = e / NB, c = e % NB;
            Ad[r][c] = A[(size_t)(j0 + r) * NP + j0 + c];
        }
        __syncthreads();
        if (tid < 32) {
            int lane = tid;
            float v = z[j0 + lane];
            for (int j = 0; j < NB; ++j) {
                if (lane == j) v /= Ad[j][j];
                float zj = __shfl_sync(0xffffffffu, v, j);
                if (lane > j) v -= Ad[lane][j] * zj;
            }
            z[j0 + lane] = v;
        }
        __syncthreads();
        for (int i = j0 + NB + tid; i < NP; i += 256) {
            float s = 0.f;
            const float* arow = &A[(size_t)i * NP + j0];
#pragma unroll
            for (int k = 0; k < NB; ++k) s = fmaf(arow[k], z[j0 + k], s);
            z[i] -= s;
        }
        __syncthreads();
    }

    for (int p = NP / NB - 1; p >= 0; --p) {
        int j0 = p * NB;
        for (int e = tid; e < NB * NB; e += 256) {
            int r = e / NB, c = e % NB;
            Ad[r][c] = A[(size_t)(j0 + r) * NP + j0 + c];
        }
        __syncthreads();
        if (tid < 32) {
            int lane = tid;
            float v = z[j0 + lane];
            for (int j = NB - 1; j >= 0; --j) {
                if (lane == j) v /= Ad[j][j];
                float wj = __shfl_sync(0xffffffffu, v, j);
                if (lane < j) v -= Ad[j][lane] * wj;
            }
            z[j0 + lane] = v;
        }
        __syncthreads();
        for (int i = tid; i < j0; i += 256) {
            float s = 0.f;
#pragma unroll
            for (int k = 0; k < NB; ++k)
                s = fmaf(A[(size_t)(j0 + k) * NP + i], z[j0 + k], s);
            z[i] -= s;
        }
        __syncthreads();
    }

    for (int i = tid; i < NP; i += 256) g_w[b * NP + i] = z[i];
}

/* ---------------- prediction: y = (tr @ w) * std + mean --------------- */
__global__ void __launch_bounds__(256) predict_kernel(float* __restrict__ out) {
    int warp = threadIdx.x >> 5, lane = threadIdx.x & 31;
    int row = blockIdx.x * 8 + warp;
    int b = row >> 10;
    __shared__ float ws[NP];
    for (int i = threadIdx.x; i < NP; i += 256) ws[i] = g_w[b * NP + i];
    __syncthreads();

    const float* f = g_bufF + ((size_t)NCTX + row) * 512;
    float s = 0.f;
    for (int c = lane * 4; c < 512; c += 128) {
        float4 v = *(const float4*)&f[c];
        s += v.x * ws[c] + v.y * ws[c + 1] + v.z * ws[c + 2] + v.w * ws[c + 3];
    }
#pragma unroll
    for (int o = 16; o > 0; o >>= 1) s += __shfl_down_sync(0xffffffffu, s, o);
    if (lane == 0) {
        s += ws[512];
        float mean = g_stats[b * 2], stdv = g_stats[b * 2 + 1];
        out[row] = s * stdv + mean;
    }
}

/* ---------------------------- launcher -------------------------------- */
extern "C" void kernel_launch(void* const* d_in, const int* in_sizes, int n_in,
                              void* d_out, int out_size) {
    const float* xc  = (const float*)d_in[0];
    const float* y   = (const float*)d_in[1];
    const float* xt  = (const float*)d_in[2];
    const float* W0  = (const float*)d_in[3];
    const float* b0  = (const float*)d_in[4];
    const float* W1  = (const float*)d_in[5];
    const float* b1  = (const float*)d_in[6];
    const float* W2  = (const float*)d_in[7];
    const float* b2  = (const float*)d_in[8];
    const float* Wr  = (const float*)d_in[9];
    const float* br  = (const float*)d_in[10];
    const float* lnv = (const float*)d_in[11];
    float* out = (float*)d_out;
    (void)in_sizes; (void)n_in; (void)out_size;

    cudaFuncSetAttribute(mma_gemm<true, false>,
                         cudaFuncAttributeMaxDynamicSharedMemorySize, GEMM_SMEM);
    cudaFuncSetAttribute(mma_gemm<false, true>,
                         cudaFuncAttributeMaxDynamicSharedMemorySize, GEMM_SMEM);
    cudaFuncSetAttribute(cholesky_kernel,
                         cudaFuncAttributeMaxDynamicSharedMemorySize, CHOL_SMEM);

    __half *hA, *hB, *w1h, *w2h, *wrh;
    float* bufF;
    cudaGetSymbolAddress((void**)&hA, g_hA);
    cudaGetSymbolAddress((void**)&hB, g_hB);
    cudaGetSymbolAddress((void**)&w1h, g_W1h);
    cudaGetSymbolAddress((void**)&w2h, g_W2h);
    cudaGetSymbolAddress((void**)&wrh, g_Wrh);
    cudaGetSymbolAddress((void**)&bufF, g_bufF);

    prep_w_kernel<<<1024, 256>>>(W1, W2, Wr);
    pt_init_kernel<<<16384, 256>>>();
    layer0_kernel<<<(NPTS * 512) / 256, 256>>>(xc, xt, W0, b0);

    dim3 ggrid(4, NPTS / 128);
    mma_gemm<true, false><<<ggrid, 256, GEMM_SMEM>>>(hA, w1h, b1, hB, nullptr);
    mma_gemm<true, false><<<ggrid, 256, GEMM_SMEM>>>(hB, w2h, b2, hA, nullptr);
    mma_gemm<false, true><<<ggrid, 256, GEMM_SMEM>>>(hA, wrh, br, nullptr, bufF);

    stats_xty_kernel<<<BATCH, 512>>>(y);
    dim3 cgrid(45, BATCH);
    cov_mma<<<cgrid, 256>>>(lnv);
    cholesky_kernel<<<BATCH, 256, CHOL_SMEM>>>();
    solve_kernel<<<BATCH, 256>>>();
    predict_kernel<<<NCTX / 8, 256>>>(out);
}

// round 16
// speedup vs baseline: 1.5425x; 1.0907x over previous
#include <cuda_runtime.h>
#include <cuda_fp16.h>
#include <math.h>
#include <stdint.h>

#define BATCH 64
#define NCC   1024
#define NTT   1024
#define HID   512
#define NPTS  (BATCH*(NCC+NTT))   /* 131072 */
#define NCTX  (BATCH*NCC)         /* 65536  */
#define NP    576                 /* padded 513 -> 576 = 18*32 */
#define NB    32
#define MAXM  544                 /* largest trailing panel rows */

/* ------------------- global scratch (static, no allocs) --------------- */
__device__ __half g_hA[(size_t)NPTS*HID];
__device__ __half g_hB[(size_t)NPTS*HID];
__device__ __half g_PT[(size_t)BATCH*NP*NCC];  /* PhiT [b][r][n] */
__device__ __half g_panH[(size_t)BATCH*MAXM*NB];
__device__ __half g_panL[(size_t)BATCH*MAXM*NB];
__device__ __half g_W1h[HID*HID];
__device__ __half g_W2h[HID*HID];
__device__ __half g_Wrh[HID*HID];
__device__ float g_cov [(size_t)BATCH*NP*NP];
__device__ float g_xty [BATCH*NP];
__device__ float g_w   [BATCH*NP];
__device__ float g_stats[BATCH*2];

/* ----------------------- PTX helpers (sm_80-era only) ----------------- */
__device__ __forceinline__ uint32_t smem_u32(const void* p) {
    uint32_t a;
    asm("{ .reg .u64 t; cvta.to.shared.u64 t, %1; cvt.u32.u64 %0, t; }" : "=r"(a) : "l"(p));
    return a;
}

__device__ __forceinline__ void cp16(uint32_t dst, const void* src) {
    asm volatile("cp.async.cg.shared.global [%0], [%1], 16;" :: "r"(dst), "l"(src));
}
#define CP_COMMIT() asm volatile("cp.async.commit_group;" ::: "memory")
#define CP_WAIT(n)  asm volatile("cp.async.wait_group %0;" :: "n"(n) : "memory")

__device__ __forceinline__ void ldsm_x4(uint32_t* r, uint32_t addr) {
    asm volatile("ldmatrix.sync.aligned.m8n8.x4.shared.b16 {%0,%1,%2,%3}, [%4];"
        : "=r"(r[0]), "=r"(r[1]), "=r"(r[2]), "=r"(r[3]) : "r"(addr));
}
__device__ __forceinline__ void ldsm_x2(uint32_t* r, uint32_t addr) {
    asm volatile("ldmatrix.sync.aligned.m8n8.x2.shared.b16 {%0,%1}, [%2];"
        : "=r"(r[0]), "=r"(r[1]) : "r"(addr));
}

__device__ __forceinline__ void mma16816(float* c,
        uint32_t a0, uint32_t a1, uint32_t a2, uint32_t a3,
        uint32_t b0, uint32_t b1) {
    asm volatile(
        "mma.sync.aligned.m16n8k16.row.col.f32.f16.f16.f32 "
        "{%0,%1,%2,%3}, {%4,%5,%6,%7}, {%8,%9}, {%0,%1,%2,%3};"
        : "+f"(c[0]), "+f"(c[1]), "+f"(c[2]), "+f"(c[3])
        : "r"(a0), "r"(a1), "r"(a2), "r"(a3), "r"(b0), "r"(b1));
}

/* polynomial sine (deg-9 Taylor, |x|<=2, err<5e-5) — pure FMA */
__device__ __forceinline__ float sin_poly(float x) {
    float x2 = x * x;
    float p = fmaf(x2, 2.75573192e-6f, -1.98412698e-4f);
    p = fmaf(x2, p, 8.33333333e-3f);
    p = fmaf(x2, p, -1.66666667e-1f);
    return fmaf(x * x2, p, x);
}

__device__ __forceinline__ float sin_cw(float arg) {
    float k = rintf(arg * 0.3183098861837907f);
    float r = fmaf(-k, 3.14159274101257324e+0f, arg);
    r = fmaf(-k, -8.74227765734758577e-8f, r);
    float s = sin_poly(r);
    int ki = (int)k;
    return (ki & 1) ? -s : s;
}

/* ---------------- layer 0: h0 = sin(30*(x*W0 + b0)) ------------------- */
__global__ void layer0_kernel(const float* __restrict__ xc,
                              const float* __restrict__ xt,
                              const float* __restrict__ W0,
                              const float* __restrict__ b0) {
    size_t idx = (size_t)blockIdx.x * blockDim.x + threadIdx.x;
    int p = (int)(idx >> 9);
    int j = (int)(idx & 511);
    float x = (p < NCTX) ? xc[p] : xt[p - NCTX];
    float arg = 30.0f * fmaf(x, W0[j], b0[j]);
    g_hA[idx] = __float2half_rn(sin_cw(arg));
}

/* ------------- weight prep ------------------------------------------- */
__global__ void prep_w_kernel(const float* __restrict__ W1,
                              const float* __restrict__ W2,
                              const float* __restrict__ Wr) {
    int i = blockIdx.x * 256 + threadIdx.x;
    int k = i >> 9, n = i & 511;
    g_W1h[n * 512 + k] = __float2half_rn(W1[i]);
    g_W2h[n * 512 + k] = __float2half_rn(W2[i]);
    g_Wrh[n * 512 + k] = __float2half_rn(Wr[i]);
}

/* ---- init PhiT rows 512..575 ---------------------------------------- */
__global__ void pt_init_kernel() {
    int i = blockIdx.x * 256 + threadIdx.x;
    int n   = i & 1023;
    int row = (i >> 10) & 63;
    int b   = i >> 16;
    size_t o = ((size_t)b * NP + 512 + row) * 1024 + n;
    g_PT[o] = __float2half_rn(row == 0 ? 1.0f : 0.0f);
}

/* -------- HMMA fp16 GEMM: C = act(A @ W + bias) ----------------------- */
#define LDS 40
#define ARR_ELEMS (128*LDS)
#define STAGE_ELEMS (2*ARR_ELEMS)
#define NSTG 3
#define GEMM_SMEM (NSTG*STAGE_ELEMS*2)

template<bool SIN, bool LAST>
__global__ void __launch_bounds__(256, 2) mma_gemm(
    const __half* __restrict__ A,
    const __half* __restrict__ Wh,
    const float* __restrict__ bias,
    __half* __restrict__ O)
{
    extern __shared__ __half sm[];
    int tid = threadIdx.x;
    int lane = tid & 31, wid = tid >> 5;
    int wm = wid >> 2, wn = wid & 3;
    int m0 = blockIdx.y * 128;
    int n0 = blockIdx.x * 128;

    uint32_t sbase = smem_u32(sm);

    float acc[4][4][4];
#pragma unroll
    for (int a = 0; a < 4; a++)
#pragma unroll
        for (int b = 0; b < 4; b++)
#pragma unroll
            for (int c = 0; c < 4; c++) acc[a][b][c] = 0.f;

    int r0i = tid >> 2,         c80 = (tid & 3) * 8;
    int r1i = (tid + 256) >> 2;

    auto issue = [&](int kt) {
        uint32_t st = sbase + (uint32_t)(kt % NSTG) * STAGE_ELEMS * 2;
#pragma unroll
        for (int h = 0; h < 2; ++h) {
            int row = h ? r1i : r0i;
            size_t ga = (size_t)(m0 + row) * 512 + kt * 32 + c80;
            size_t gb = (size_t)(n0 + row) * 512 + kt * 32 + c80;
            uint32_t so = (uint32_t)(row * LDS + c80) * 2;
            cp16(st + 0 * ARR_ELEMS * 2 + so, A + ga);
            cp16(st + 1 * ARR_ELEMS * 2 + so, Wh + gb);
        }
    };

    issue(0); CP_COMMIT();
    issue(1); CP_COMMIT();

    for (int kt = 0; kt < 16; ++kt) {
        if (kt < 14) {
            issue(kt + 2);
            CP_COMMIT();
            CP_WAIT(2);
        } else if (kt == 14) {
            CP_WAIT(1);
        } else {
            CP_WAIT(0);
        }
        __syncthreads();

        uint32_t st = sbase + (uint32_t)(kt % NSTG) * STAGE_ELEMS * 2;
        uint32_t arowA = (uint32_t)((wm * 64 + (lane & 15)) * LDS) * 2;
        uint32_t acolA = (uint32_t)((lane >> 4) * 8) * 2;
        uint32_t browB = (uint32_t)((wn * 32 + (lane & 7)) * LDS) * 2;
        uint32_t bcolB = (uint32_t)(((lane >> 3) & 1) * 8) * 2;

#pragma unroll
        for (int ks = 0; ks < 2; ++ks) {
            uint32_t ah[4][4], bh[4][2];
            uint32_t kofs = (uint32_t)(ks * 16) * 2;
#pragma unroll
            for (int mt = 0; mt < 4; ++mt)
                ldsm_x4(ah[mt], st + arowA + (uint32_t)(mt * 16 * LDS) * 2 + acolA + kofs);
#pragma unroll
            for (int nt = 0; nt < 4; ++nt)
                ldsm_x2(bh[nt], st + ARR_ELEMS * 2 + browB + (uint32_t)(nt * 8 * LDS) * 2 + bcolB + kofs);
#pragma unroll
            for (int mt = 0; mt < 4; ++mt)
#pragma unroll
                for (int nt = 0; nt < 4; ++nt)
                    mma16816(acc[mt][nt], ah[mt][0], ah[mt][1], ah[mt][2], ah[mt][3], bh[nt][0], bh[nt][1]);
        }
        __syncthreads();
    }

    /* ---------------- epilogue ---------------- */
#pragma unroll
    for (int nt = 0; nt < 4; ++nt) {
        int col = n0 + wn * 32 + nt * 8 + (lane & 3) * 2;
        float bv0 = __ldg(bias + col);
        float bv1 = __ldg(bias + col + 1);
#pragma unroll
        for (int mt = 0; mt < 4; ++mt) {
            int row = m0 + wm * 64 + mt * 16 + (lane >> 2);
#pragma unroll
            for (int half = 0; half < 2; ++half) {
                int r = row + half * 8;
                float v0 = acc[mt][nt][half * 2 + 0] + bv0;
                float v1 = acc[mt][nt][half * 2 + 1] + bv1;
                size_t go = (size_t)r * 512 + col;
                if (LAST && r < NCTX) {      /* context -> transposed fp16 */
                    int b = r >> 10, n = r & 1023;
                    size_t o0 = ((size_t)b * NP + col) * 1024 + n;
                    g_PT[o0]        = __float2half_rn(v0);
                    g_PT[o0 + 1024] = __float2half_rn(v1);
                } else {
                    if (!LAST && SIN) { v0 = sin_poly(v0); v1 = sin_poly(v1); }
                    __half h0 = __float2half_rn(v0);
                    __half h1 = __float2half_rn(v1);
                    uint32_t uh = ((uint32_t)__half_as_ushort(h1) << 16) | __half_as_ushort(h0);
                    *(uint32_t*)(O + go) = uh;   /* LAST: fp16 target features */
                }
            }
        }
    }
}

/* ---------------- per-batch stats (mean/std) + xty from fp16 PT ------- */
__device__ __forceinline__ float block_reduce_512(float v, float* red, int tid) {
    red[tid] = v; __syncthreads();
    for (int s = 256; s > 0; s >>= 1) {
        if (tid < s) red[tid] += red[tid + s];
        __syncthreads();
    }
    float r = red[0];
    __syncthreads();
    return r;
}

__global__ void __launch_bounds__(512) stats_xty_kernel(const float* __restrict__ y) {
    int b = blockIdx.x;
    int tid = threadIdx.x;
    __shared__ float yc[1024];
    __shared__ float red[512];

    float y0 = y[b * 1024 + tid];
    float y1 = y[b * 1024 + 512 + tid];
    float sum   = block_reduce_512(y0 + y1, red, tid);
    float sumsq = block_reduce_512(y0 * y0 + y1 * y1, red, tid);

    float mean = sum / 1024.0f;
    float var  = (sumsq - sum * sum / 1024.0f) / 1023.0f;
    float stdv = sqrtf(var);
    float inv  = 1.0f / stdv;
    yc[tid]       = (y0 - mean) * inv;
    yc[tid + 512] = (y1 - mean) * inv;
    if (tid == 0) { g_stats[b * 2] = mean; g_stats[b * 2 + 1] = stdv; }
    __syncthreads();

    float sy = block_reduce_512(yc[tid] + yc[tid + 512], red, tid);

    const __half* Pb = g_PT + (size_t)b * NP * 1024;
    int warp = tid >> 5, lane = tid & 31;
    for (int r = warp; r < 512; r += 16) {
        const __half* rowp = Pb + (size_t)r * 1024;
        float acc = 0.f;
#pragma unroll 4
        for (int n = lane * 2; n < 1024; n += 64) {
            __half2 h2 = *(const __half2*)(rowp + n);
            float2 f = __half22float2(h2);
            acc = fmaf(f.x, yc[n], acc);
            acc = fmaf(f.y, yc[n + 1], acc);
        }
#pragma unroll
        for (int o = 16; o > 0; o >>= 1) acc += __shfl_down_sync(0xffffffffu, acc, o);
        if (lane == 0) g_xty[b * NP + r] = acc;
    }
    if (tid == 0) g_xty[b * NP + 512] = sy;
    if (tid < NP - 513) g_xty[b * NP + 513 + tid] = 0.0f;
}

/* -------- cov = PhiT PhiT^T + noise*I via fp16 HMMA ------------------- */
#define CLDS 40
#define CARR (64*CLDS)
#define CSTAGE (2*CARR)

__global__ void __launch_bounds__(256, 2) cov_mma(const float* __restrict__ log_noise) {
    __shared__ __half sm[NSTG * CSTAGE];
    int b = blockIdx.y;
    int t = blockIdx.x;
    int ti = 0;
    while ((ti + 1) * (ti + 2) / 2 <= t) ti++;
    int tj = t - ti * (ti + 1) / 2;
    int r0 = ti * 64, s0 = tj * 64;

    const __half* Ph = g_PT + (size_t)b * NP * 1024;

    int tid = threadIdx.x, lane = tid & 31, wid = tid >> 5;
    int wm = wid >> 2, wn = wid & 3;
    uint32_t sbase = smem_u32(sm);

    float acc[2][2][4];
#pragma unroll
    for (int a = 0; a < 2; a++)
#pragma unroll
        for (int c = 0; c < 2; c++)
#pragma unroll
            for (int d = 0; d < 4; d++) acc[a][c][d] = 0.f;

    int lrow = tid >> 2, lc8 = (tid & 3) * 8;

    auto issue = [&](int kt) {
        uint32_t st = sbase + (uint32_t)(kt % NSTG) * CSTAGE * 2;
        size_t ga = (size_t)(r0 + lrow) * 1024 + kt * 32 + lc8;
        size_t gb = (size_t)(s0 + lrow) * 1024 + kt * 32 + lc8;
        uint32_t so = (uint32_t)(lrow * CLDS + lc8) * 2;
        cp16(st + 0 * CARR * 2 + so, Ph + ga);
        cp16(st + 1 * CARR * 2 + so, Ph + gb);
    };

    issue(0); CP_COMMIT();
    issue(1); CP_COMMIT();

    for (int kt = 0; kt < 32; ++kt) {
        if (kt < 30) {
            issue(kt + 2);
            CP_COMMIT();
            CP_WAIT(2);
        } else if (kt == 30) {
            CP_WAIT(1);
        } else {
            CP_WAIT(0);
        }
        __syncthreads();

        uint32_t st = sbase + (uint32_t)(kt % NSTG) * CSTAGE * 2;
        uint32_t arow = (uint32_t)((wm * 32 + (lane & 15)) * CLDS) * 2;
        uint32_t acol = (uint32_t)((lane >> 4) * 8) * 2;
        uint32_t brow = (uint32_t)((wn * 16 + (lane & 7)) * CLDS) * 2;
        uint32_t bcol = (uint32_t)(((lane >> 3) & 1) * 8) * 2;

#pragma unroll
        for (int ks = 0; ks < 2; ++ks) {
            uint32_t ah[2][4], bh[2][2];
            uint32_t kofs = (uint32_t)(ks * 16) * 2;
#pragma unroll
            for (int mt = 0; mt < 2; ++mt)
                ldsm_x4(ah[mt], st + arow + (uint32_t)(mt * 16 * CLDS) * 2 + acol + kofs);
#pragma unroll
            for (int nt = 0; nt < 2; ++nt)
                ldsm_x2(bh[nt], st + CARR * 2 + brow + (uint32_t)(nt * 8 * CLDS) * 2 + bcol + kofs);
#pragma unroll
            for (int mt = 0; mt < 2; ++mt)
#pragma unroll
                for (int nt = 0; nt < 2; ++nt)
                    mma16816(acc[mt][nt], ah[mt][0], ah[mt][1], ah[mt][2], ah[mt][3], bh[nt][0], bh[nt][1]);
        }
        __syncthreads();
    }

    float noise = expf(log_noise[0]);
    float* Cv = g_cov + (size_t)b * NP * NP;
#pragma unroll
    for (int nt = 0; nt < 2; ++nt) {
        int c = s0 + wn * 16 + nt * 8 + (lane & 3) * 2;
#pragma unroll
        for (int mt = 0; mt < 2; ++mt) {
            int rb = r0 + wm * 32 + mt * 16 + (lane >> 2);
#pragma unroll
            for (int half = 0; half < 2; ++half) {
                int r = rb + half * 8;
                float v0 = acc[mt][nt][half * 2 + 0];
                float v1 = acc[mt][nt][half * 2 + 1];
                if (r == c)     v0 = (r <= 512) ? v0 + noise : 1.0f;
                if (r == c + 1) v1 = (r <= 512) ? v1 + noise : 1.0f;
                Cv[(size_t)r * NP + c]     = v0;
                Cv[(size_t)r * NP + c + 1] = v1;
            }
        }
    }
}

/* ---- Cholesky panel: diag factor + panel solve (one CTA per batch) --- */
__global__ void __launch_bounds__(256) panel_kernel(int p) {
    __shared__ float Ad[NB][NB + 1];
    __shared__ float invd[NB];
    int b = blockIdx.x;
    int tid = threadIdx.x, lane = tid & 31;
    float* A = g_cov + (size_t)b * NP * NP;
    int j0 = p * NB;

    for (int e = tid; e < NB * NB; e += 256) {
        int r = e >> 5, c = e & 31;
        Ad[r][c] = A[(size_t)(j0 + r) * NP + j0 + c];
    }
    __syncthreads();
    if (tid < 32) {
        for (int j = 0; j < NB; ++j) {
            if (lane == j) {
                float d = sqrtf(Ad[j][j]);
                Ad[j][j] = d;
                invd[j] = 1.0f / d;
            }
            __syncwarp();
            float inv = invd[j];
            if (lane > j) Ad[lane][j] *= inv;
            __syncwarp();
            if (lane > j) {
                float lij = Ad[lane][j];
                for (int k = j + 1; k <= lane; ++k)
                    Ad[lane][k] -= lij * Ad[k][j];
            }
            __syncwarp();
        }
    }
    __syncthreads();
    for (int e = tid; e < NB * NB; e += 256) {
        int r = e >> 5, c = e & 31;
        A[(size_t)(j0 + r) * NP + j0 + c] = Ad[r][c];
    }

    /* panel solve with reciprocal multiplies; emit fp16 hi/lo planes */
    __half* pH = g_panH + (size_t)b * MAXM * NB;
    __half* pL = g_panL + (size_t)b * MAXM * NB;
    for (int i = j0 + NB + tid; i < NP; i += 256) {
        float x[NB];
        float* arow = &A[(size_t)i * NP + j0];
#pragma unroll
        for (int j = 0; j < NB; ++j) x[j] = arow[j];
#pragma unroll
        for (int j = 0; j < NB; ++j) {
            float s = x[j];
#pragma unroll
            for (int k = 0; k < NB; ++k)
                if (k < j) s -= x[k] * Ad[j][k];
            x[j] = s * invd[j];
        }
        int pr = i - j0 - NB;
#pragma unroll
        for (int j = 0; j < NB; ++j) {
            arow[j] = x[j];
            __half h = __float2half_rn(x[j]);
            pH[pr * NB + j] = h;
            pL[pr * NB + j] = __float2half_rn(x[j] - __half2float(h));
        }
    }
}

/* ---- SYRK: A[trail] -= L21 L21^T, tiles spread over whole chip ------- */
#define PLDS 40
#define SYRK_SMEM (MAXM*PLDS*2*2)   /* 87040 bytes */

__global__ void __launch_bounds__(256, 1) syrk_kernel(int p) {
    extern __shared__ __half ssm[];
    __half* sH = ssm;
    __half* sL = ssm + MAXM * PLDS;
    uint32_t pHb = smem_u32(sH);
    uint32_t pLb = smem_u32(sL);

    int j0 = p * NB;
    int base = j0 + NB;
    int m = NP - base;
    int T = m >> 5;
    int b = blockIdx.y;
    int tid = threadIdx.x, lane = tid & 31, wid = tid >> 5;

    /* cooperative load of hi/lo panel rows into smem */
    const __half* gH = g_panH + (size_t)b * MAXM * NB;
    const __half* gL = g_panL + (size_t)b * MAXM * NB;
    int nchunk = m * 4;                       /* 16B chunks per plane */
    for (int i = tid; i < nchunk; i += 256) {
        int row = i >> 2, q = i & 3;
        uint32_t so = (uint32_t)(row * PLDS + q * 8) * 2;
        cp16(pHb + so, gH + row * NB + q * 8);
        cp16(pLb + so, gL + row * NB + q * 8);
    }
    CP_COMMIT(); CP_WAIT(0);
    __syncthreads();

    int npairs = T * (T + 1) / 2;
    int pi = blockIdx.x * 8 + wid;
    if (pi >= npairs) return;
    int ti = 0;
    while ((ti + 1) * (ti + 2) / 2 <= pi) ti++;
    int tk = pi - ti * (ti + 1) / 2;

    float* A = g_cov + (size_t)b * NP * NP;
    float acc[2][4][4];
#pragma unroll
    for (int a = 0; a < 2; a++)
#pragma unroll
        for (int b2 = 0; b2 < 4; b2++)
#pragma unroll
            for (int c = 0; c < 4; c++) acc[a][b2][c] = 0.f;

#pragma unroll
    for (int pass = 0; pass < 2; ++pass) {
        uint32_t ab = pass ? pLb : pHb;
#pragma unroll
        for (int ks = 0; ks < 2; ++ks) {
            uint32_t kofs = (uint32_t)(ks * 16) * 2;
            uint32_t ah[2][4], bh[4][2];
#pragma unroll
            for (int mt = 0; mt < 2; ++mt) {
                uint32_t row = (uint32_t)(ti * 32 + mt * 16 + (lane & 15));
                ldsm_x4(ah[mt], ab + (row * PLDS) * 2 + (uint32_t)((lane >> 4) * 8) * 2 + kofs);
            }
#pragma unroll
            for (int nt = 0; nt < 4; ++nt) {
                uint32_t row = (uint32_t)(tk * 32 + nt * 8 + (lane & 7));
                ldsm_x2(bh[nt], pHb + (row * PLDS) * 2 + (uint32_t)(((lane >> 3) & 1) * 8) * 2 + kofs);
            }
#pragma unroll
            for (int mt = 0; mt < 2; ++mt)
#pragma unroll
                for (int nt = 0; nt < 4; ++nt)
                    mma16816(acc[mt][nt], ah[mt][0], ah[mt][1], ah[mt][2], ah[mt][3],
                             bh[nt][0], bh[nt][1]);
        }
    }
#pragma unroll
    for (int mt = 0; mt < 2; ++mt) {
#pragma unroll
        for (int half = 0; half < 2; ++half) {
            int gr = base + ti * 32 + mt * 16 + (lane >> 2) + half * 8;
#pragma unroll
            for (int nt = 0; nt < 4; ++nt) {
                int gc = base + tk * 32 + nt * 8 + (lane & 3) * 2;
                float u0 = acc[mt][nt][half * 2 + 0];
                float u1 = acc[mt][nt][half * 2 + 1];
                if (ti != tk || gc <= gr)
                    A[(size_t)gr * NP + gc] -= u0;
                if (ti != tk || gc + 1 <= gr)
                    A[(size_t)gr * NP + gc + 1] -= u1;
            }
        }
    }
}

/* ---------------- forward + backward triangular solves ---------------- */
__global__ void __launch_bounds__(256) solve_kernel() {
    int b = blockIdx.x;
    const float* A = g_cov + (size_t)b * NP * NP;
    int tid = threadIdx.x;
    __shared__ float z[NP];
    __shared__ float Ad[NB][NB + 1];
    __shared__ float invd[NB];

    for (int i = tid; i < NP; i += 256) z[i] = g_xty[b * NP + i];
    __syncthreads();

    for (int p = 0; p < NP / NB; ++p) {
        int j0 = p * NB;
        for (int e = tid; e < NB * NB; e += 256) {
            int r = e / NB, c = e % NB;
            Ad[r][c] = A[(size_t)(j0 + r) * NP + j0 + c];
        }
        __syncthreads();
        if (tid < 32) invd[tid] = 1.0f / Ad[tid][tid];
        __syncthreads();
        if (tid < 32) {
            int lane = tid;
            float v = z[j0 + lane];
            for (int j = 0; j < NB; ++j) {
                if (lane == j) v *= invd[j];
                float zj = __shfl_sync(0xffffffffu, v, j);
                if (lane > j) v -= Ad[lane][j] * zj;
            }
            z[j0 + lane] = v;
        }
        __syncthreads();
        for (int i = j0 + NB + tid; i < NP; i += 256) {
            float s = 0.f;
            const float* arow = &A[(size_t)i * NP + j0];
#pragma unroll
            for (int k = 0; k < NB; ++k) s = fmaf(arow[k], z[j0 + k], s);
            z[i] -= s;
        }
        __syncthreads();
    }

    for (int p = NP / NB - 1; p >= 0; --p) {
        int j0 = p * NB;
        for (int e = tid; e < NB * NB; e += 256) {
            int r = e / NB, c = e % NB;
            Ad[r][c] = A[(size_t)(j0 + r) * NP + j0 + c];
        }
        __syncthreads();
        if (tid < 32) invd[tid] = 1.0f / Ad[tid][tid];
        __syncthreads();
        if (tid < 32) {
            int lane = tid;
            float v = z[j0 + lane];
            for (int j = NB - 1; j >= 0; --j) {
                if (lane == j) v *= invd[j];
                float wj = __shfl_sync(0xffffffffu, v, j);
                if (lane < j) v -= Ad[j][lane] * wj;
            }
            z[j0 + lane] = v;
        }
        __syncthreads();
        for (int i = tid; i < j0; i += 256) {
            float s = 0.f;
#pragma unroll
            for (int k = 0; k < NB; ++k)
                s = fmaf(A[(size_t)(j0 + k) * NP + i], z[j0 + k], s);
            z[i] -= s;
        }
        __syncthreads();
    }

    for (int i = tid; i < NP; i += 256) g_w[b * NP + i] = z[i];
}

/* ---------------- prediction from fp16 target features ---------------- */
__global__ void __launch_bounds__(256) predict_kernel(float* __restrict__ out) {
    int warp = threadIdx.x >> 5, lane = threadIdx.x & 31;
    int row = blockIdx.x * 8 + warp;
    int b = row >> 10;
    __shared__ float ws[NP];
    for (int i = threadIdx.x; i < NP; i += 256) ws[i] = g_w[b * NP + i];
    __syncthreads();

    const __half* f = g_hB + ((size_t)NCTX + row) * 512;
    float s = 0.f;
#pragma unroll
    for (int c0 = lane * 8; c0 < 512; c0 += 256) {
        uint4 u = *(const uint4*)(f + c0);
        const __half2* hp = (const __half2*)&u;
#pragma unroll
        for (int t = 0; t < 4; ++t) {
            float2 q = __half22float2(hp[t]);
            s = fmaf(q.x, ws[c0 + 2 * t], s);
            s = fmaf(q.y, ws[c0 + 2 * t + 1], s);
        }
    }
#pragma unroll
    for (int o = 16; o > 0; o >>= 1) s += __shfl_down_sync(0xffffffffu, s, o);
    if (lane == 0) {
        s += ws[512];
        float mean = g_stats[b * 2], stdv = g_stats[b * 2 + 1];
        out[row] = s * stdv + mean;
    }
}

/* ---------------------------- launcher -------------------------------- */
extern "C" void kernel_launch(void* const* d_in, const int* in_sizes, int n_in,
                              void* d_out, int out_size) {
    const float* xc  = (const float*)d_in[0];
    const float* y   = (const float*)d_in[1];
    const float* xt  = (const float*)d_in[2];
    const float* W0  = (const float*)d_in[3];
    const float* b0  = (const float*)d_in[4];
    const float* W1  = (const float*)d_in[5];
    const float* b1  = (const float*)d_in[6];
    const float* W2  = (const float*)d_in[7];
    const float* b2  = (const float*)d_in[8];
    const float* Wr  = (const float*)d_in[9];
    const float* br  = (const float*)d_in[10];
    const float* lnv = (const float*)d_in[11];
    float* out = (float*)d_out;
    (void)in_sizes; (void)n_in; (void)out_size;

    cudaFuncSetAttribute(mma_gemm<true, false>,
                         cudaFuncAttributeMaxDynamicSharedMemorySize, GEMM_SMEM);
    cudaFuncSetAttribute(mma_gemm<false, true>,
                         cudaFuncAttributeMaxDynamicSharedMemorySize, GEMM_SMEM);
    cudaFuncSetAttribute(syrk_kernel,
                         cudaFuncAttributeMaxDynamicSharedMemorySize, SYRK_SMEM);

    __half *hA, *hB, *w1h, *w2h, *wrh;
    cudaGetSymbolAddress((void**)&hA, g_hA);
    cudaGetSymbolAddress((void**)&hB, g_hB);
    cudaGetSymbolAddress((void**)&w1h, g_W1h);
    cudaGetSymbolAddress((void**)&w2h, g_W2h);
    cudaGetSymbolAddress((void**)&wrh, g_Wrh);

    prep_w_kernel<<<1024, 256>>>(W1, W2, Wr);
    pt_init_kernel<<<16384, 256>>>();
    layer0_kernel<<<(NPTS * 512) / 256, 256>>>(xc, xt, W0, b0);

    dim3 ggrid(4, NPTS / 128);
    mma_gemm<true, false><<<ggrid, 256, GEMM_SMEM>>>(hA, w1h, b1, hB);
    mma_gemm<true, false><<<ggrid, 256, GEMM_SMEM>>>(hB, w2h, b2, hA);
    mma_gemm<false, true><<<ggrid, 256, GEMM_SMEM>>>(hA, wrh, br, hB);

    stats_xty_kernel<<<BATCH, 512>>>(y);
    dim3 cgrid(45, BATCH);
    cov_mma<<<cgrid, 256>>>(lnv);

    for (int p = 0; p < NP / NB; ++p) {
        panel_kernel<<<BATCH, 256>>>(p);
        int m = NP - p * NB - NB;
        if (m > 0) {
            int T = m >> 5;
            int npairs = T * (T + 1) / 2;
            dim3 sgrid((npairs + 7) / 8, BATCH);
            syrk_kernel<<<sgrid, 256, SYRK_SMEM>>>(p);
        }
    }
    solve_kernel<<<BATCH, 256>>>();
    predict_kernel<<<NCTX / 8, 256>>>(out);
}